// round 15
// baseline (speedup 1.0000x reference)
#include <cuda_runtime.h>

// RoPE3DEncoder: T=32, H=64, W=64, DIM=192 (DIM_X=DIM_Y=DIM_T=64).
// All three per-axis inv_freq tables are identical (d=64 each), so a single
// 64-position x 64-col cos/sin table (second 32 cols duplicate the first)
// covers every axis. Output: cos [131072 x 192] f32 followed by sin.
//
// FINAL — empirical write-roofline kernel: 201MB / ~29us = ~6.9 TB/s
// effective (86% of 8 TB/s HBM3e spec). Fourteen structural variants
// measured (STG.128 / STG.256 / TMA bulk stores; default / .cs /
// evict_last cache policies; 1x-16x table reuse; 1 or 2 stores per
// thread; 256/512-thread blocks; 30-86% occupancy; 4-40% issue rate):
// all converge at 28.9-30.4us kernel time. The pure write stream is the
// binding resource; no SM-side or cache-policy lever moves it.
//  - cos/sin table generated at COMPILE TIME (constexpr f64 series with an
//    f32 angle pipeline matching the reference; rel_err ~1.5e-7)
//  - one float4 quad per thread, two st.global.cs streaming stores
//    (evict-first: output is written once and never read)

#define ROWS 131072               // 32*64*64
#define NQ   (ROWS * 48)          // float4 quads per table

// ---------------- compile-time math ----------------
constexpr double K_PI  = 3.14159265358979323846264338327950288;
constexpr double K_LN2 = 0.69314718055994530941723212145818;

constexpr double cexp(double x) {
    int n = 0; double y = x;
    while (y < -0.35) { y += K_LN2; n--; }
    while (y >  0.35) { y -= K_LN2; n++; }
    double term = 1.0, s = 1.0;
    for (int i = 1; i < 26; i++) { term *= y / i; s += term; }
    while (n < 0) { s *= 0.5; n++; }
    while (n > 0) { s *= 2.0; n--; }
    return s;
}
constexpr double csin(double x) {
    double tp = 2.0 * K_PI;
    long long k = (long long)(x / tp + 0.5);
    double y = x - (double)k * tp;          // [-pi, pi]
    double y2 = y * y, term = y, s = y;
    for (int i = 1; i < 16; i++) {
        term *= -y2 / (double)((2 * i) * (2 * i + 1));
        s += term;
    }
    return s;
}
constexpr double ccos(double x) { return csin(x + K_PI * 0.5); }

struct alignas(16) Tab { float c[64 * 64]; float s[64 * 64]; };

constexpr Tab make_tab() {
    Tab t{};
    for (int pos = 0; pos < 64; pos++) {
        for (int j = 0; j < 32; j++) {
            float invf = (float)cexp(-9.210340371976184 * (double)j / 32.0);
            float ang  = (float)pos * invf;       // match reference f32 pipeline
            float cv = (float)ccos((double)ang);
            float sv = (float)csin((double)ang);
            t.c[pos * 64 + j]      = cv;
            t.c[pos * 64 + j + 32] = cv;
            t.s[pos * 64 + j]      = sv;
            t.s[pos * 64 + j + 32] = sv;
        }
    }
    return t;
}

constexpr Tab H_TAB = make_tab();
__device__ const Tab g_tab = H_TAB;

// ---------------- fill kernel ----------------
__global__ void __launch_bounds__(256) rope_fill(float4* __restrict__ out) {
    unsigned idx = blockIdx.x * blockDim.x + threadIdx.x;   // quad index
    unsigned row = idx / 48u;              // ptxas -> umulhi, cheap
    unsigned q   = idx - row * 48u;
    unsigned c4  = q * 4u;                 // starting column of this quad

    unsigned w = row & 63u;
    unsigned h = (row >> 6) & 63u;
    unsigned t = row >> 12;

    // Quads never straddle the 64/128 axis boundaries.
    unsigned pos = (c4 < 64u) ? w : ((c4 < 128u) ? h : t);
    unsigned off = (pos * 64u + (c4 & 63u)) >> 2;   // quad offset in table

    float4 vc = reinterpret_cast<const float4*>(g_tab.c)[off];
    float4 vs = reinterpret_cast<const float4*>(g_tab.s)[off];

    __stcs(out + idx,      vc);   // cos half, streaming (evict-first)
    __stcs(out + NQ + idx, vs);   // sin half, streaming
}

extern "C" void kernel_launch(void* const* d_in, const int* in_sizes, int n_in,
                              void* d_out, int out_size) {
    (void)d_in; (void)in_sizes; (void)n_in; (void)out_size;
    // 6,291,456 quads / 256 = 24576 blocks, exact
    rope_fill<<<NQ / 256, 256>>>(reinterpret_cast<float4*>(d_out));
}

// round 16
// speedup vs baseline: 1.0092x; 1.0092x over previous
#include <cuda_runtime.h>

// RoPE3DEncoder: T=32, H=64, W=64, DIM=192 (DIM_X=DIM_Y=DIM_T=64).
// All three per-axis inv_freq tables are identical (d=64 each), so a single
// 64-position x 64-col cos/sin table (second 32 cols duplicate the first)
// covers every axis. Output: cos [131072 x 192] f32 followed by sin.
//
// FINAL — empirical write-roofline kernel: 201MB / ~29us = ~6.9 TB/s
// effective (86% of 8 TB/s HBM3e spec). Fifteen structural variants
// measured across five axes (store engine: STG.128 / STG.256 / TMA bulk;
// cache policy: default / .cs / evict_last pinning; table reuse: 1x-16x,
// SMEM staging; thread mapping: 1-2 stores/thread; launch geometry:
// 256/512 threads, 12K-49K CTAs, 30-86% occupancy, 4-40% issue): all
// converge at 28.9-30.4us kernel time. The pure write stream is the
// binding resource; nothing SM-side or cache-policy-side moves it.
//  - cos/sin table generated at COMPILE TIME (constexpr f64 series with an
//    f32 angle pipeline matching the reference; rel_err ~1.5e-7)
//  - one float4 quad per thread, two st.global.cs streaming stores
//    (evict-first: output is written once and never read)

#define ROWS 131072               // 32*64*64
#define NQ   (ROWS * 48)          // float4 quads per table

// ---------------- compile-time math ----------------
constexpr double K_PI  = 3.14159265358979323846264338327950288;
constexpr double K_LN2 = 0.69314718055994530941723212145818;

constexpr double cexp(double x) {
    int n = 0; double y = x;
    while (y < -0.35) { y += K_LN2; n--; }
    while (y >  0.35) { y -= K_LN2; n++; }
    double term = 1.0, s = 1.0;
    for (int i = 1; i < 26; i++) { term *= y / i; s += term; }
    while (n < 0) { s *= 0.5; n++; }
    while (n > 0) { s *= 2.0; n--; }
    return s;
}
constexpr double csin(double x) {
    double tp = 2.0 * K_PI;
    long long k = (long long)(x / tp + 0.5);
    double y = x - (double)k * tp;          // [-pi, pi]
    double y2 = y * y, term = y, s = y;
    for (int i = 1; i < 16; i++) {
        term *= -y2 / (double)((2 * i) * (2 * i + 1));
        s += term;
    }
    return s;
}
constexpr double ccos(double x) { return csin(x + K_PI * 0.5); }

struct alignas(16) Tab { float c[64 * 64]; float s[64 * 64]; };

constexpr Tab make_tab() {
    Tab t{};
    for (int pos = 0; pos < 64; pos++) {
        for (int j = 0; j < 32; j++) {
            float invf = (float)cexp(-9.210340371976184 * (double)j / 32.0);
            float ang  = (float)pos * invf;       // match reference f32 pipeline
            float cv = (float)ccos((double)ang);
            float sv = (float)csin((double)ang);
            t.c[pos * 64 + j]      = cv;
            t.c[pos * 64 + j + 32] = cv;
            t.s[pos * 64 + j]      = sv;
            t.s[pos * 64 + j + 32] = sv;
        }
    }
    return t;
}

constexpr Tab H_TAB = make_tab();
__device__ const Tab g_tab = H_TAB;

// ---------------- fill kernel ----------------
__global__ void __launch_bounds__(256) rope_fill(float4* __restrict__ out) {
    unsigned idx = blockIdx.x * blockDim.x + threadIdx.x;   // quad index
    unsigned row = idx / 48u;              // ptxas -> umulhi, cheap
    unsigned q   = idx - row * 48u;
    unsigned c4  = q * 4u;                 // starting column of this quad

    unsigned w = row & 63u;
    unsigned h = (row >> 6) & 63u;
    unsigned t = row >> 12;

    // Quads never straddle the 64/128 axis boundaries.
    unsigned pos = (c4 < 64u) ? w : ((c4 < 128u) ? h : t);
    unsigned off = (pos * 64u + (c4 & 63u)) >> 2;   // quad offset in table

    float4 vc = reinterpret_cast<const float4*>(g_tab.c)[off];
    float4 vs = reinterpret_cast<const float4*>(g_tab.s)[off];

    __stcs(out + idx,      vc);   // cos half, streaming (evict-first)
    __stcs(out + NQ + idx, vs);   // sin half, streaming
}

extern "C" void kernel_launch(void* const* d_in, const int* in_sizes, int n_in,
                              void* d_out, int out_size) {
    (void)d_in; (void)in_sizes; (void)n_in; (void)out_size;
    // 6,291,456 quads / 256 = 24576 blocks, exact
    rope_fill<<<NQ / 256, 256>>>(reinterpret_cast<float4*>(d_out));
}

// round 17
// speedup vs baseline: 1.0312x; 1.0219x over previous
#include <cuda_runtime.h>

// RoPE3DEncoder: T=32, H=64, W=64, DIM=192 (DIM_X=DIM_Y=DIM_T=64).
// All three per-axis inv_freq tables are identical (d=64 each), so a single
// 64-position x 64-col cos/sin table (second 32 cols duplicate the first)
// covers every axis. Output: cos [131072 x 192] f32 followed by sin.
//
// FINAL — empirical write-roofline kernel: 201MB / ~29us = ~6.9 TB/s
// effective (86% of 8 TB/s HBM3e spec). Sixteen structural variants
// measured across five axes (store engine: STG.128 / STG.256 / TMA bulk;
// cache policy: default / .cs / evict_last pinning; table reuse: 1x-16x,
// SMEM staging; thread mapping: 1-2 stores/thread; launch geometry:
// 256/512 threads, 12K-49K CTAs, 30-86% occupancy, 4-40% issue): all
// converge at 28.9-30.4us kernel time. The pure write stream is the
// binding resource; nothing SM-side or cache-policy-side moves it.
//  - cos/sin table generated at COMPILE TIME (constexpr f64 series with an
//    f32 angle pipeline matching the reference; rel_err ~1.5e-7)
//  - one float4 quad per thread, two st.global.cs streaming stores
//    (evict-first: output is written once and never read)

#define ROWS 131072               // 32*64*64
#define NQ   (ROWS * 48)          // float4 quads per table

// ---------------- compile-time math ----------------
constexpr double K_PI  = 3.14159265358979323846264338327950288;
constexpr double K_LN2 = 0.69314718055994530941723212145818;

constexpr double cexp(double x) {
    int n = 0; double y = x;
    while (y < -0.35) { y += K_LN2; n--; }
    while (y >  0.35) { y -= K_LN2; n++; }
    double term = 1.0, s = 1.0;
    for (int i = 1; i < 26; i++) { term *= y / i; s += term; }
    while (n < 0) { s *= 0.5; n++; }
    while (n > 0) { s *= 2.0; n--; }
    return s;
}
constexpr double csin(double x) {
    double tp = 2.0 * K_PI;
    long long k = (long long)(x / tp + 0.5);
    double y = x - (double)k * tp;          // [-pi, pi]
    double y2 = y * y, term = y, s = y;
    for (int i = 1; i < 16; i++) {
        term *= -y2 / (double)((2 * i) * (2 * i + 1));
        s += term;
    }
    return s;
}
constexpr double ccos(double x) { return csin(x + K_PI * 0.5); }

struct alignas(16) Tab { float c[64 * 64]; float s[64 * 64]; };

constexpr Tab make_tab() {
    Tab t{};
    for (int pos = 0; pos < 64; pos++) {
        for (int j = 0; j < 32; j++) {
            float invf = (float)cexp(-9.210340371976184 * (double)j / 32.0);
            float ang  = (float)pos * invf;       // match reference f32 pipeline
            float cv = (float)ccos((double)ang);
            float sv = (float)csin((double)ang);
            t.c[pos * 64 + j]      = cv;
            t.c[pos * 64 + j + 32] = cv;
            t.s[pos * 64 + j]      = sv;
            t.s[pos * 64 + j + 32] = sv;
        }
    }
    return t;
}

constexpr Tab H_TAB = make_tab();
__device__ const Tab g_tab = H_TAB;

// ---------------- fill kernel ----------------
__global__ void __launch_bounds__(256) rope_fill(float4* __restrict__ out) {
    unsigned idx = blockIdx.x * blockDim.x + threadIdx.x;   // quad index
    unsigned row = idx / 48u;              // ptxas -> umulhi, cheap
    unsigned q   = idx - row * 48u;
    unsigned c4  = q * 4u;                 // starting column of this quad

    unsigned w = row & 63u;
    unsigned h = (row >> 6) & 63u;
    unsigned t = row >> 12;

    // Quads never straddle the 64/128 axis boundaries.
    unsigned pos = (c4 < 64u) ? w : ((c4 < 128u) ? h : t);
    unsigned off = (pos * 64u + (c4 & 63u)) >> 2;   // quad offset in table

    float4 vc = reinterpret_cast<const float4*>(g_tab.c)[off];
    float4 vs = reinterpret_cast<const float4*>(g_tab.s)[off];

    __stcs(out + idx,      vc);   // cos half, streaming (evict-first)
    __stcs(out + NQ + idx, vs);   // sin half, streaming
}

extern "C" void kernel_launch(void* const* d_in, const int* in_sizes, int n_in,
                              void* d_out, int out_size) {
    (void)d_in; (void)in_sizes; (void)n_in; (void)out_size;
    // 6,291,456 quads / 256 = 24576 blocks, exact
    rope_fill<<<NQ / 256, 256>>>(reinterpret_cast<float4*>(d_out));
}